// round 6
// baseline (speedup 1.0000x reference)
#include <cuda_runtime.h>
#include <math.h>

#define NB 4
#define CC 64
#define HH 64
#define WW 64
#define LL 4096
#define FF 256

#define OUT_S 0
#define OUT_U 16384
#define OUT_R 32768
#define OUT_A 9469952

typedef unsigned long long ull;

__device__ float g_Ut[NB][FF][LL];        // normalized features, k-major
__device__ float g_Utd[NB][FF][2 * LL];   // same, each value duplicated (for B)
__device__ float g_P[NB][HH][WW];
__device__ float g_rnorm[NB][LL];
__device__ int   g_arg[NB][LL];
__device__ ull   g_best[NB][LL];          // packed (sortable(v)<<32) | ~l

__device__ __constant__ int c_dy[4] = {-1, -1, -1, 0};
__device__ __constant__ int c_dx[4] = {-1,  0,  1, -1};

// packed-f32x2 FMA: two fp32 FMAs per instruction, bit-identical per lane
#define FMA2(d, a, b) asm("fma.rn.f32x2 %0, %1, %2, %0;" : "+l"(d) : "l"(a), "l"(b))

#define CP16(dst, src) asm volatile( \
    "cp.async.cg.shared.global [%0], [%1], 16;" :: "r"(dst), "l"(src))
#define CP_COMMIT() asm volatile("cp.async.commit_group;")
#define CP_WAIT0()  asm volatile("cp.async.wait_group 0;")

__device__ __forceinline__ unsigned sortable(float v) {
    unsigned u = __float_as_uint(v);
    return (u & 0x80000000u) ? ~u : (u | 0x80000000u);
}
__device__ __forceinline__ float unsortable(unsigned s) {
    unsigned u = (s & 0x80000000u) ? (s ^ 0x80000000u) : ~s;
    return __uint_as_float(u);
}

// ---------------------------------------------------------------------------
__global__ void kP(const float* __restrict__ yhat) {
    int b = blockIdx.x;
    int n = b >> 6, y = b & 63;
    int x = threadIdx.x;
    const float* p = yhat + (((long)n * CC) * HH + y) * WW + x;
    float s = 0.f;
    #pragma unroll 8
    for (int c = 0; c < CC; ++c) {
        float v = p[(long)c * HH * WW];
        s += v * v;
    }
    g_P[n][y][x] = s;
}

__global__ void kNorm() {
    int idx = blockIdx.x * blockDim.x + threadIdx.x;
    int n = idx >> 12, l = idx & 4095;
    int y = l >> 6, x = l & 63;
    float s = 0.f;
    #pragma unroll
    for (int o = 0; o < 4; ++o) {
        int yy = y + c_dy[o], xx = x + c_dx[o];
        if (yy >= 0 && xx >= 0 && xx < WW) s += g_P[n][yy][xx];
    }
    float nrm = fmaxf(sqrtf(s), 1e-12f);
    g_rnorm[n][l] = 1.0f / nrm;
    ((ull*)g_best)[idx] = 0ull;        // reset packed-best each replay
}

__global__ void kBuild(const float* __restrict__ yhat) {
    int e = blockIdx.x * blockDim.x + threadIdx.x;
    int l = e & 4095;
    int f = (e >> 12) & 255;
    int n = e >> 20;
    int y = l >> 6, x = l & 63;
    int off = f >> 6, c = f & 63;
    int yy = y + c_dy[off], xx = x + c_dx[off];
    float v = 0.f;
    if (yy >= 0 && xx >= 0 && xx < WW)
        v = yhat[(((long)n * CC + c) * HH + yy) * WW + xx];
    v *= g_rnorm[n][l];
    g_Ut[n][f][l] = v;
    float2 d; d.x = v; d.y = v;
    ((float2*)g_Utd)[(((long)n * FF + f) << 12) + l] = d;   // duplicated pair
}

// ---------------------------------------------------------------------------
// Triangular max-argmax GEMM. One 128x128 tile per block, k=256 in chunks of
// 16, double-buffered cp.async. 8x8 microtile, pure f32x2 FMAs (B read
// pre-duplicated from g_Utd -> no lane-dup movs in the inner loop).
__global__ void __launch_bounds__(256) kGemm() {
    // stage s (6144 floats): A [16][128] at s*6144, Bdup [16][256] at +2048
    __shared__ __align__(16) float sm[12288];

    int n = blockIdx.y;
    int b = blockIdx.x;                 // b = mt*(mt+1)/2 + lt
    int mt = (int)((sqrtf(8.f * b + 1.f) - 1.f) * 0.5f);
    while ((mt + 1) * (mt + 2) / 2 <= b) ++mt;
    while (mt * (mt + 1) / 2 > b) --mt;
    int lt = b - mt * (mt + 1) / 2;
    int m0 = mt << 7, l0 = lt << 7;

    const float* __restrict__ Ut  = &g_Ut[n][0][0];
    const float* __restrict__ Utd = &g_Utd[n][0][0];

    int tid  = threadIdx.x;
    int w    = tid >> 5, lane = tid & 31;
    int tx   = ((w & 3) << 2) | (lane & 3);    // 0..15 (4 distinct per warp)
    int ty   = ((w >> 2) << 3) | (lane >> 2);  // 0..15 (8 distinct per warp)
    int row  = tid >> 4;                       // load row 0..15
    int c0   = tid & 15;                       // load float4 col base

    unsigned sbase = (unsigned)__cvta_generic_to_shared(sm);

    // prefetch chunk 0 into stage 0
    {
        const float* ga = Ut  + (long)row * LL + l0;
        const float* gb = Utd + ((long)row * LL << 1) + (m0 << 1);
        unsigned da = sbase + ((row << 7) << 2);
        unsigned db = sbase + ((2048 + (row << 8)) << 2);
        #pragma unroll
        for (int q = 0; q < 2; ++q) {
            int c4 = c0 + (q << 4);
            CP16(da + (c4 << 4), ga + (c4 << 2));
        }
        #pragma unroll
        for (int q = 0; q < 4; ++q) {
            int c4 = c0 + (q << 4);
            CP16(db + (c4 << 4), gb + (c4 << 2));
        }
        CP_COMMIT();
    }

    ull acc[4][8];
    #pragma unroll
    for (int i = 0; i < 4; ++i)
        #pragma unroll
        for (int j = 0; j < 8; ++j) acc[i][j] = 0ull;

    #pragma unroll 1
    for (int kc = 0; kc < 16; ++kc) {
        CP_WAIT0();
        __syncthreads();

        if (kc < 15) {                  // prefetch next chunk into other stage
            int k0 = (kc + 1) << 4;
            unsigned sdst = sbase + ((((kc + 1) & 1) * 6144) << 2);
            const float* ga = Ut  + (long)(k0 + row) * LL + l0;
            const float* gb = Utd + ((long)(k0 + row) * LL << 1) + (m0 << 1);
            unsigned da = sdst + ((row << 7) << 2);
            unsigned db = sdst + ((2048 + (row << 8)) << 2);
            #pragma unroll
            for (int q = 0; q < 2; ++q) {
                int c4 = c0 + (q << 4);
                CP16(da + (c4 << 4), ga + (c4 << 2));
            }
            #pragma unroll
            for (int q = 0; q < 4; ++q) {
                int c4 = c0 + (q << 4);
                CP16(db + (c4 << 4), gb + (c4 << 2));
            }
            CP_COMMIT();
        }

        const float* bufA = sm + (kc & 1) * 6144;
        const float* bufB = bufA + 2048;
        #pragma unroll
        for (int k = 0; k < 16; ++k) {
            const float* ra = bufA + (k << 7);
            const float* rb = bufB + (k << 8);
            ulonglong2 A0 = *(const ulonglong2*)(ra + (ty << 2));
            ulonglong2 A1 = *(const ulonglong2*)(ra + 64 + (ty << 2));
            ulonglong2 Bq0 = *(const ulonglong2*)(rb + (tx << 3));
            ulonglong2 Bq1 = *(const ulonglong2*)(rb + (tx << 3) + 4);
            ulonglong2 Bq2 = *(const ulonglong2*)(rb + 128 + (tx << 3));
            ulonglong2 Bq3 = *(const ulonglong2*)(rb + 128 + (tx << 3) + 4);
            ull ap[4] = {A0.x, A0.y, A1.x, A1.y};
            ull bp[8] = {Bq0.x, Bq0.y, Bq1.x, Bq1.y,
                         Bq2.x, Bq2.y, Bq3.x, Bq3.y};
            #pragma unroll
            for (int j = 0; j < 8; ++j)
                #pragma unroll
                for (int i = 0; i < 4; ++i) FMA2(acc[i][j], ap[i], bp[j]);
        }
    }

    // fold into per-thread best (causal l < m, first-occurrence ties)
    float bestv[8];
    int   bestl[8];
    #pragma unroll
    for (int j = 0; j < 8; ++j) { bestv[j] = -INFINITY; bestl[j] = 0x7fffffff; }

    #pragma unroll
    for (int j = 0; j < 8; ++j) {
        int m = m0 + ((j < 4) ? (tx << 2) + j : 64 + (tx << 2) + (j - 4));
        #pragma unroll
        for (int p = 0; p < 4; ++p) {
            int lb = l0 + ((p < 2) ? (ty << 2) + p * 2
                                   : 64 + (ty << 2) + (p - 2) * 2);
            ull a = acc[p][j];
            float v0 = __uint_as_float((unsigned)(a & 0xffffffffu));
            float v1 = __uint_as_float((unsigned)(a >> 32));
            if (lb < m && (v0 > bestv[j] || (v0 == bestv[j] && lb < bestl[j]))) {
                bestv[j] = v0; bestl[j] = lb;
            }
            int l1 = lb + 1;
            if (l1 < m && (v1 > bestv[j] || (v1 == bestv[j] && l1 < bestl[j]))) {
                bestv[j] = v1; bestl[j] = l1;
            }
        }
    }

    // cross-ty reduction in smem, then one packed atomicMax per m-column
    __syncthreads();
    float* rv = sm;                    // [128][16]
    int*   rl = (int*)(sm + 2048);     // [128][16]
    #pragma unroll
    for (int j = 0; j < 8; ++j) {
        int col = (j < 4) ? (tx << 2) + j : 64 + (tx << 2) + (j - 4);
        rv[col * 16 + ty] = bestv[j];
        rl[col * 16 + ty] = bestl[j];
    }
    __syncthreads();
    if (tid < 128) {
        float bv = rv[tid * 16];
        int   bl = rl[tid * 16];
        #pragma unroll
        for (int u = 1; u < 16; ++u) {
            float v = rv[tid * 16 + u];
            int   l = rl[tid * 16 + u];
            if (v > bv || (v == bv && l < bl)) { bv = v; bl = l; }
        }
        bv += 0.0f;                    // canonicalize -0.0 -> +0.0
        ull key = ((ull)sortable(bv) << 32) | (unsigned)(~bl);
        atomicMax(&g_best[n][m0 + tid], key);
    }
}

// ---------------------------------------------------------------------------
__global__ void kFinal(const float* __restrict__ yprob, float* __restrict__ out) {
    int idx = blockIdx.x * blockDim.x + threadIdx.x;   // n*LL + m
    int n = idx >> 12, m = idx & 4095;
    float S, U, A;
    int bl;
    if (m == 0) {
        S = 1e-8f; U = 1e-8f; A = -1.f; bl = -1;
    } else {
        ull key = g_best[n][m];
        float bv = unsortable((unsigned)(key >> 32));
        bl = (int)(~(unsigned)(key & 0xffffffffu));
        if (bv < 0.f) { bv = 0.f; bl = m; }
        S = fminf(fmaxf(bv, 1e-8f), 1.0f);
        U = fminf(fmaxf(yprob[n * LL + bl], 1e-8f), 1.0f);
        A = (float)bl;
    }
    g_arg[n][m] = bl;
    out[OUT_S + idx] = S;
    out[OUT_U + idx] = U;
    out[OUT_A + idx] = A;
}

__global__ void kOut(const float* __restrict__ yhat, float* __restrict__ out) {
    long e = (long)blockIdx.x * blockDim.x + threadIdx.x;
    int m = (int)(e & 4095);
    int t = (int)(e >> 12);
    int f = t % 576;
    int n = t / 576;
    float v = 0.f;
    if (m != 0) {
        int a  = g_arg[n][m];
        int c  = f / 9, ij = f % 9;
        int i  = ij / 3, j = ij % 3;
        int ay = a >> 6, ax = a & 63;
        int yy = ay + i - 1, xx = ax + j - 1;
        if (yy >= 0 && yy < HH && xx >= 0 && xx < WW)
            v = yhat[(((long)n * CC + c) * HH + yy) * WW + xx];
    }
    out[OUT_R + e] = v;
}

// ---------------------------------------------------------------------------
extern "C" void kernel_launch(void* const* d_in, const int* in_sizes, int n_in,
                              void* d_out, int out_size) {
    const float* yhat  = (const float*)d_in[0];
    const float* yprob = (const float*)d_in[1];
    float* out = (float*)d_out;

    kP<<<NB * HH, WW>>>(yhat);
    kNorm<<<(NB * LL) / 256, 256>>>();
    kBuild<<<(NB * FF * LL) / 256, 256>>>(yhat);
    kGemm<<<dim3(528, NB), 256>>>();
    kFinal<<<(NB * LL) / 256, 256>>>(yprob, out);
    kOut<<<(NB * 576 * LL) / 256, 256>>>(yhat, out);
}